// round 2
// baseline (speedup 1.0000x reference)
#include <cuda_runtime.h>

// Problem constants (fixed shapes per reference: residuals (2,1,4096,4096))
#define H 4096
#define W 4096
#define HW (H * W)
#define NBINS (1 << 20)   // top-20-bit sortable-key histogram

// Scratch (device globals: no allocation allowed in kernel_launch)
__device__ unsigned int g_hist[NBINS];
__device__ unsigned int g_part[1024];
__device__ float        g_median;

// ---- float <-> monotone sortable key ----
__device__ __forceinline__ unsigned int f2key(float f) {
    unsigned int u = __float_as_uint(f);
    return (u & 0x80000000u) ? ~u : (u | 0x80000000u);
}
__device__ __forceinline__ float key2f(unsigned int k) {
    unsigned int u = (k & 0x80000000u) ? (k ^ 0x80000000u) : ~k;
    return __uint_as_float(u);
}

// ---- 1) zero the histogram (graph replays require re-zeroing every launch) ----
__global__ void zero_hist_kernel() {
    g_hist[blockIdx.x * blockDim.x + threadIdx.x] = 0u;
}

// ---- 2) histogram of r0 keys (top 20 bits) ----
__global__ void hist_kernel(const float4* __restrict__ r0) {
    const int n4 = HW / 4;
    const int stride = gridDim.x * blockDim.x;
    for (int i = blockIdx.x * blockDim.x + threadIdx.x; i < n4; i += stride) {
        float4 v = r0[i];
        atomicAdd(&g_hist[f2key(v.x) >> 12], 1u);
        atomicAdd(&g_hist[f2key(v.y) >> 12], 1u);
        atomicAdd(&g_hist[f2key(v.z) >> 12], 1u);
        atomicAdd(&g_hist[f2key(v.w) >> 12], 1u);
    }
}

// ---- 3) per-chunk partial sums (1024 chunks of 1024 bins) ----
__global__ void part_kernel() {
    __shared__ unsigned int s[256];
    const int base = blockIdx.x * 1024;
    unsigned int sum = 0;
    for (int j = threadIdx.x; j < 1024; j += 256) sum += g_hist[base + j];
    s[threadIdx.x] = sum;
    __syncthreads();
    for (int off = 128; off > 0; off >>= 1) {
        if (threadIdx.x < off) s[threadIdx.x] += s[threadIdx.x + off];
        __syncthreads();
    }
    if (threadIdx.x == 0) g_part[blockIdx.x] = s[0];
}

// ---- 4) locate the two middle ranks, reconstruct median ----
__global__ void pick_kernel() {
    __shared__ unsigned int sp[1024];
    __shared__ unsigned int sincl[1024];
    __shared__ float sv[2];
    const int t = threadIdx.x;
    unsigned int v = g_part[t];
    sp[t] = v;
    sincl[t] = v;
    __syncthreads();
    // Hillis-Steele inclusive scan
    for (int off = 1; off < 1024; off <<= 1) {
        unsigned int add = (t >= off) ? sincl[t - off] : 0u;
        __syncthreads();
        sincl[t] += add;
        __syncthreads();
    }
    const unsigned int incl = sincl[t];
    const unsigned int excl = incl - sp[t];
    const unsigned int ranks[2] = {HW / 2 - 1, HW / 2};  // even count: average two middles
    for (int ri = 0; ri < 2; ri++) {
        unsigned int k = ranks[ri];
        if (k >= excl && k < incl) {
            unsigned int c = excl;
            for (int j = 0; j < 1024; j++) {
                unsigned int hcnt = g_hist[t * 1024 + j];
                if (k < c + hcnt) {
                    unsigned int key = ((unsigned int)(t * 1024 + j) << 12) | 0x800u;  // bin midpoint
                    sv[ri] = key2f(key);
                    break;
                }
                c += hcnt;
            }
        }
    }
    __syncthreads();
    if (t == 0) g_median = 0.5f * (sv[0] + sv[1]);
}

// ---- 5) fused: 3x3 box (zero SAME) + 16x16/s8 box (edge pad) + upsample + mask + linear+sigmoid
#define TS    64
#define RROWS 74     // r0 halo tile (64 + 2*5): has needs +-4, its 3x3 needs +-1
#define RSTR  76
#define HROWS 72     // has tile (64 + 2*4) for patch windows
#define HSTR  76

__global__ __launch_bounds__(256) void fused_kernel(
    const float* __restrict__ res,   // residuals: [2, H, W]
    const float* __restrict__ w1,    // [2]
    const float* __restrict__ b1,    // [1]
    float* __restrict__ out,         // [HW] gated, (+[HW] mask if write_mask)
    int write_mask)
{
    __shared__ float sr[RROWS * RSTR];   // (r0 - m), zero outside image
    __shared__ float sh[HROWS * HSTR];   // 3x3 box of sr
    __shared__ float spatch[64];         // 8x8 patch values for this tile

    const float m = g_median;
    const int gy0 = blockIdx.y * TS;
    const int gx0 = blockIdx.x * TS;
    const int tid = threadIdx.x;

    // Load (r0 - m) with zero for out-of-image (implements SAME zero padding of inlier_loss)
    for (int i = tid; i < RROWS * RROWS; i += 256) {
        int lr = i / RROWS, lc = i - lr * RROWS;
        int gr = gy0 - 5 + lr, gc = gx0 - 5 + lc;
        float v = 0.f;
        if ((unsigned)gr < (unsigned)H && (unsigned)gc < (unsigned)W)
            v = res[gr * W + gc] - m;
        sr[lr * RSTR + lc] = v;
    }
    __syncthreads();

    // has = 3x3 mean. sh row lr <-> global row gy0-4+lr <-> sr row lr+1
    for (int i = tid; i < HROWS * HROWS; i += 256) {
        int lr = i / HROWS, lc = i - lr * HROWS;
        const float* p = &sr[lr * RSTR + lc];  // window rows lr..lr+2, cols lc..lc+2
        float s = p[0] + p[1] + p[2]
                + p[RSTR] + p[RSTR + 1] + p[RSTR + 2]
                + p[2 * RSTR] + p[2 * RSTR + 1] + p[2 * RSTR + 2];
        sh[lr * HSTR + lc] = s * (1.f / 9.f);
    }
    __syncthreads();

    // 8x8 patches: 16x16 mean of `has` with replicate-clamped window rows/cols
    if (tid < 64) {
        int py = tid >> 3, px = tid & 7;
        float s = 0.f;
        for (int wr = 0; wr < 16; wr++) {
            int gr = gy0 + py * 8 - 4 + wr;
            gr = min(max(gr, 0), H - 1);
            const float* row = &sh[(gr - gy0 + 4) * HSTR];
            for (int wc = 0; wc < 16; wc++) {
                int gc = gx0 + px * 8 - 4 + wc;
                gc = min(max(gc, 0), W - 1);
                s += row[gc - gx0 + 4];
            }
        }
        spatch[tid] = s * (1.f / 256.f);
    }
    __syncthreads();

    const float w00 = w1[0], w01 = w1[1], b = b1[0];
    const float4* r1 = (const float4*)(res + HW);

    const int cq = tid & 15;   // x = cq*4
    const int rb = tid >> 4;   // row within 16-row slab
    for (int k = 0; k < 4; k++) {
        int y = rb + k * 16;
        int x = cq * 4;
        int gy = gy0 + y, gx = gx0 + x;
        float4 rv = r1[(gy * W + gx) >> 2];
        float rr[4] = {rv.x, rv.y, rv.z, rv.w};
        float4 mo, oo;
        float* mp = &mo.x;
        float* op = &oo.x;
        int py = y >> 3;
        #pragma unroll
        for (int j = 0; j < 4; j++) {
            int xx = x + j;
            float mask = spatch[py * 8 + (xx >> 3)]
                       + sh[(y + 4) * HSTR + xx + 4]
                       + sr[(y + 5) * RSTR + xx + 5];
            float z = rr[j] * w00 + mask * w01 + b;
            op[j] = 1.f / (1.f + __expf(-z));
            mp[j] = mask;
        }
        int o = gy * W + gx;
        *(float4*)(out + o) = oo;
        if (write_mask) *(float4*)(out + HW + o) = mo;
    }
}

extern "C" void kernel_launch(void* const* d_in, const int* in_sizes, int n_in,
                              void* d_out, int out_size) {
    const float* res = (const float*)d_in[0];   // (2,1,4096,4096) f32
    const float* w1  = (const float*)d_in[1];   // (1,2) f32
    const float* b1  = (const float*)d_in[2];   // (1,) f32
    float* out = (float*)d_out;

    zero_hist_kernel<<<NBINS / 256, 256>>>();
    hist_kernel<<<2048, 256>>>((const float4*)res);
    part_kernel<<<1024, 256>>>();
    pick_kernel<<<1, 1024>>>();

    int write_mask = (out_size >= 2 * HW) ? 1 : 0;
    dim3 grid(W / TS, H / TS);
    fused_kernel<<<grid, 256>>>(res, w1, b1, out, write_mask);
}